// round 6
// baseline (speedup 1.0000x reference)
#include <cuda_runtime.h>

// ---------------------------------------------------------------------------
// CTC loss (forward, sum over batch, zero_infinity) on GB300 — two-phase,
// single-warp LOG2-domain scan (registers only, no barriers, no smem).
//
// Phase 1 (ctc_emit_kernel): em[t][b][l] = logp[t][b][ext_b[l]] * log2(e),
//   stored interleaved g_em[z*LPAD + r*32 + lane], column l = lane*R + r,
//   z = t*B + b. Invalid columns (>= 2*target_len+1) get 0.0 (their trellis
//   cells stay quarantined at -1e30 via float absorption and are never read).
//
// Phase 2 (ctc_alpha_kernel): ONE WARP per batch element, lane i owns columns
//   [i*R, i*R+R). log2-alphas in registers; cross-lane halo via 2 shfl_up per
//   step; lse3 with exact median-of-3 so both ex2 args <= 0 (no overflow, no
//   NaN, unlimited dynamic range). Emit rows prefetched PF=6 deep, coalesced.
// ---------------------------------------------------------------------------

#define NEGF (-1.0e30f)
#define LOG2E 1.4426950408889634f
#define LN2   0.6931471805599453f
#define R     7
#define LPAD  (32 * R)                  // 224 padded columns
#define EM_CAP (1000 * 32 * LPAD)

__device__ __align__(128) float g_em[EM_CAP];
__device__ float g_loss[8192];

__device__ __forceinline__ float ex2f(float x) {
    float r; asm("ex2.approx.f32 %0, %1;" : "=f"(r) : "f"(x)); return r;
}
__device__ __forceinline__ float lg2f(float x) {
    float r; asm("lg2.approx.f32 %0, %1;" : "=f"(r) : "f"(x)); return r;
}

// lse3 in log2 domain; exact median-of-3 -> ex2 args provably <= 0.
__device__ __forceinline__ float lse3_2(float a0, float a1, float a2) {
    const float mx01 = fmaxf(a0, a1);
    const float mn01 = fminf(a0, a1);
    const float mx   = fmaxf(mx01, a2);
    const float md   = fmaxf(mn01, fminf(mx01, a2));
    const float mn   = fminf(mn01, a2);
    const float s    = 1.0f + ex2f(md - mx) + ex2f(mn - mx);
    return mx + lg2f(s);
}

// ---- Phase 1: emit gather (log2 units), one CTA per (t, b) pair ------------
__global__ void ctc_emit_kernel(const float* __restrict__ logp,
                                const int*   __restrict__ targets,
                                const int*   __restrict__ target_lens,
                                int B, int C, int S, int L)
{
    const int z = blockIdx.x;          // z = t*B + b
    const int b = z % B;
    const int l = threadIdx.x;         // 0 .. LPAD-1

    const int Lb = 2 * target_lens[b] + 1;

    float p = 0.0f;
    if (l < L && l < Lb) {
        int e = 0;
        if (l & 1) e = targets[b * S + (l >> 1)];
        p = logp[(size_t)z * C + e] * LOG2E;
    }
    g_em[((size_t)z * R + (l % R)) * 32 + (l / R)] = p;
}

// ---- Phase 2: single-warp log-domain alpha scan ------------------------------
__global__ void ctc_alpha_kernel(const int* __restrict__ targets,
                                 const int* __restrict__ input_lens,
                                 const int* __restrict__ target_lens,
                                 int B, int S)
{
    const int b    = blockIdx.x;
    const int lane = threadIdx.x;
    const unsigned FULL = 0xffffffffu;

    const int tl = target_lens[b];
    const int il = input_lens[b];
    const int Lb = 2 * tl + 1;

    // Skip-transition flags for this lane's columns.
    bool sk[R];
#pragma unroll
    for (int r = 0; r < R; ++r) {
        const int l = lane * R + r;
        bool s = false;
        if ((l & 1) && l >= 3 && l < Lb) {
            const int c  = targets[b * S + (l >> 1)];
            const int pc = targets[b * S + (l >> 1) - 1];
            s = (c != pc);
        }
        sk[r] = s;
    }

    const size_t strideT = (size_t)B * LPAD;
    const float* emp = g_em + (size_t)b * LPAD + lane;   // + r*32 + t*strideT

    // t = 0 init: log-alpha = em at columns 0,1 (lane 0), else -1e30.
    float la[R];
#pragma unroll
    for (int r = 0; r < R; ++r) la[r] = NEGF;
    {
        const float e00 = emp[0];       // coalesced; only lane 0's values used
        const float e01 = emp[32];
        if (lane == 0) { la[0] = e00; la[1] = e01; }
    }

    // Emit prefetch pipeline, depth 6.
    const int PF = 6;
    float em[PF][R];
#pragma unroll
    for (int j = 0; j < PF; ++j) {
        const int t = 1 + j;
#pragma unroll
        for (int r = 0; r < R; ++r)
            em[j][r] = (t < il) ? emp[(size_t)t * strideT + r * 32] : 0.0f;
    }

    for (int tb = 1; tb < il; tb += PF) {
#pragma unroll
        for (int j = 0; j < PF; ++j) {
            const int t = tb + j;
            if (t >= il) break;                    // uniform across warp

            // Halo: left lane's two rightmost OLD log-alphas.
            float L1 = __shfl_up_sync(FULL, la[R - 1], 1);
            float L2 = __shfl_up_sync(FULL, la[R - 2], 1);
            if (lane == 0) { L1 = NEGF; L2 = NEGF; }

            // Prefetch emit row for t + PF (coalesced, L2-resident).
            const int tp = t + PF;
            float pre[R];
            if (tp < il) {
#pragma unroll
                for (int r = 0; r < R; ++r)
                    pre[r] = emp[(size_t)tp * strideT + r * 32];
            } else {
#pragma unroll
                for (int r = 0; r < R; ++r) pre[r] = 0.0f;
            }

            // In-place descending update: new la[r] uses only OLD la[<r].
#pragma unroll
            for (int r = R - 1; r >= 2; --r) {
                const float a2 = sk[r] ? la[r - 2] : NEGF;
                la[r] = lse3_2(la[r], la[r - 1], a2) + em[j][r];
            }
            {
                const float a2 = sk[1] ? L1 : NEGF;
                la[1] = lse3_2(la[1], la[0], a2) + em[j][1];
            }
            {
                const float a2 = sk[0] ? L2 : NEGF;
                la[0] = lse3_2(la[0], L1, a2) + em[j][0];
            }

#pragma unroll
            for (int r = 0; r < R; ++r) em[j][r] = pre[r];
        }
    }

    // Final cells: columns 2*tl (blank) and 2*tl-1 (last label), log2 units.
    const int c1 = 2 * tl;
    const int c2 = (tl >= 1) ? (2 * tl - 1) : 0;
    const int r1 = c1 % R, i1 = c1 / R;
    const int r2 = c2 % R, i2 = c2 / R;

    float x1 = la[0], x2 = la[0];
#pragma unroll
    for (int r = 1; r < R; ++r) {
        if (r == r1) x1 = la[r];
        if (r == r2) x2 = la[r];
    }
    x1 = __shfl_sync(FULL, x1, i1);
    x2 = __shfl_sync(FULL, x2, i2);

    if (lane == 0) {
        if (tl < 1) x2 = NEGF;
        const float m = fmaxf(x1, x2);
        float loss = -LN2 * (m + lg2f(ex2f(x1 - m) + ex2f(x2 - m)));
        if (!(loss < 5.0e29f)) loss = 0.0f;        // zero_infinity (inf/nan -> 0)
        g_loss[b] = loss;
    }
}

__global__ void ctc_reduce_kernel(float* __restrict__ out, int B)
{
    float s = 0.0f;
    for (int i = threadIdx.x; i < B; i += 32) s += g_loss[i];
#pragma unroll
    for (int o = 16; o; o >>= 1) s += __shfl_xor_sync(0xffffffffu, s, o);
    if (threadIdx.x == 0) out[0] = s;
}

extern "C" void kernel_launch(void* const* d_in, const int* in_sizes, int n_in,
                              void* d_out, int out_size)
{
    const float* logp        = (const float*)d_in[0];
    const int*   targets     = (const int*)  d_in[1];
    const int*   input_lens  = (const int*)  d_in[2];
    const int*   target_lens = (const int*)  d_in[3];

    const int B = in_sizes[2];
    const int S = in_sizes[1] / B;
    const int C = 1000;
    const int T = (int)((long long)in_sizes[0] / ((long long)B * (long long)C));

    const int L = 2 * S + 1;              // requires L <= 224 (S <= 111)

    ctc_emit_kernel<<<T * B, LPAD>>>(logp, targets, target_lens, B, C, S, L);
    ctc_alpha_kernel<<<B, 32>>>(targets, input_lens, target_lens, B, S);
    ctc_reduce_kernel<<<1, 32>>>((float*)d_out, B);
}

// round 7
// speedup vs baseline: 1.0034x; 1.0034x over previous
#include <cuda_runtime.h>

// ---------------------------------------------------------------------------
// CTC loss (forward, sum over batch, zero_infinity) on GB300 — two-phase,
// single-warp LOG2-domain scan (registers only, no barriers, no smem).
//
// Phase 1 (ctc_emit_kernel): em[t][b][l] = logp[t][b][ext_b[l]] * log2(e),
//   stored interleaved g_em[z*LPAD + r*32 + lane], column l = lane*R + r.
//
// Phase 2 (ctc_alpha_kernel): ONE WARP per batch element, lane i owns columns
//   [i*R, i*R+R). log2-alphas in registers; halo via 2 shfl_up; lse3 with
//   exact median-of-3 (ex2 args <= 0: overflow/NaN free, unbounded range).
//   KEY FIX vs prior rounds: emit prefetch loads write DIRECTLY into the
//   pipeline slot consumed PF steps later (no same-step register copy), so
//   the LDG scoreboard wait has PF full steps of cover instead of zero.
// ---------------------------------------------------------------------------

#define NEGF (-1.0e30f)
#define LOG2E 1.4426950408889634f
#define LN2   0.6931471805599453f
#define R     7
#define LPAD  (32 * R)                  // 224 padded columns
#define EM_CAP (1000 * 32 * LPAD)

__device__ __align__(128) float g_em[EM_CAP];
__device__ float g_loss[8192];

__device__ __forceinline__ float ex2f(float x) {
    float r; asm("ex2.approx.f32 %0, %1;" : "=f"(r) : "f"(x)); return r;
}
__device__ __forceinline__ float lg2f(float x) {
    float r; asm("lg2.approx.f32 %0, %1;" : "=f"(r) : "f"(x)); return r;
}

// lse3 in log2 domain; exact median-of-3 -> ex2 args provably <= 0.
__device__ __forceinline__ float lse3_2(float a0, float a1, float a2) {
    const float mx01 = fmaxf(a0, a1);
    const float mn01 = fminf(a0, a1);
    const float mx   = fmaxf(mx01, a2);
    const float md   = fmaxf(mn01, fminf(mx01, a2));
    const float mn   = fminf(mn01, a2);
    const float s    = 1.0f + ex2f(md - mx) + ex2f(mn - mx);
    return mx + lg2f(s);
}

// ---- Phase 1: emit gather (log2 units), one CTA per (t, b) pair ------------
__global__ void ctc_emit_kernel(const float* __restrict__ logp,
                                const int*   __restrict__ targets,
                                const int*   __restrict__ target_lens,
                                int B, int C, int S, int L)
{
    const int z = blockIdx.x;          // z = t*B + b
    const int b = z % B;
    const int l = threadIdx.x;         // 0 .. LPAD-1

    const int Lb = 2 * target_lens[b] + 1;

    float p = 0.0f;
    if (l < L && l < Lb) {
        int e = 0;
        if (l & 1) e = targets[b * S + (l >> 1)];
        p = logp[(size_t)z * C + e] * LOG2E;
    }
    g_em[((size_t)z * R + (l % R)) * 32 + (l / R)] = p;
}

// ---- Phase 2: single-warp log-domain alpha scan ------------------------------
__global__ void __launch_bounds__(32, 1)
ctc_alpha_kernel(const int* __restrict__ targets,
                 const int* __restrict__ input_lens,
                 const int* __restrict__ target_lens,
                 int B, int S)
{
    const int b    = blockIdx.x;
    const int lane = threadIdx.x;
    const unsigned FULL = 0xffffffffu;

    const int tl = target_lens[b];
    const int il = input_lens[b];
    const int Lb = 2 * tl + 1;

    // Skip-transition flags for this lane's columns.
    bool sk[R];
#pragma unroll
    for (int r = 0; r < R; ++r) {
        const int l = lane * R + r;
        bool s = false;
        if ((l & 1) && l >= 3 && l < Lb) {
            const int c  = targets[b * S + (l >> 1)];
            const int pc = targets[b * S + (l >> 1) - 1];
            s = (c != pc);
        }
        sk[r] = s;
    }

    const size_t strideT = (size_t)B * LPAD;
    const float* emp = g_em + (size_t)b * LPAD + lane;   // + r*32 + t*strideT

    // t = 0 init: log-alpha = em at columns 0,1 (lane 0), else -1e30.
    float la[R];
#pragma unroll
    for (int r = 0; r < R; ++r) la[r] = NEGF;
    {
        const float e00 = emp[0];       // coalesced; only lane 0's values used
        const float e01 = emp[32];
        if (lane == 0) { la[0] = e00; la[1] = e01; }
    }

    // Emit prefetch pipeline, depth 8. Slot j holds emit for the step that
    // will consume it; after consumption the SAME slot is overwritten with
    // the load for t + PF (scoreboard wait lands PF steps later).
    const int PF = 8;
    float em[PF][R];
#pragma unroll
    for (int j = 0; j < PF; ++j) {
        const int t = 1 + j;
#pragma unroll
        for (int r = 0; r < R; ++r)
            em[j][r] = (t < il) ? emp[(size_t)t * strideT + r * 32] : 0.0f;
    }

    for (int tb = 1; tb < il; tb += PF) {
#pragma unroll
        for (int j = 0; j < PF; ++j) {
            const int t = tb + j;
            if (t >= il) break;                    // uniform across warp

            // Consume this step's emit row from the pipeline slot.
            float e0 = em[j][0], e1 = em[j][1], e2c = em[j][2], e3 = em[j][3],
                  e4 = em[j][4], e5 = em[j][5], e6 = em[j][6];

            // Immediately refill the slot for t + PF (deferred wait).
            const int tp = t + PF;
            if (tp < il) {
                const float* pf = emp + (size_t)tp * strideT;
#pragma unroll
                for (int r = 0; r < R; ++r) em[j][r] = pf[r * 32];
            }

            // Halo: left lane's two rightmost OLD log-alphas.
            float L1 = __shfl_up_sync(FULL, la[R - 1], 1);
            float L2 = __shfl_up_sync(FULL, la[R - 2], 1);
            if (lane == 0) { L1 = NEGF; L2 = NEGF; }

            // In-place descending update: new la[r] uses only OLD la[<r].
            la[6] = lse3_2(la[6], la[5], sk[6] ? la[4] : NEGF) + e6;
            la[5] = lse3_2(la[5], la[4], sk[5] ? la[3] : NEGF) + e5;
            la[4] = lse3_2(la[4], la[3], sk[4] ? la[2] : NEGF) + e4;
            la[3] = lse3_2(la[3], la[2], sk[3] ? la[1] : NEGF) + e3;
            la[2] = lse3_2(la[2], la[1], sk[2] ? la[0] : NEGF) + e2c;
            la[1] = lse3_2(la[1], la[0], sk[1] ? L1    : NEGF) + e1;
            la[0] = lse3_2(la[0], L1,    sk[0] ? L2    : NEGF) + e0;
        }
    }

    // Final cells: columns 2*tl (blank) and 2*tl-1 (last label), log2 units.
    const int c1 = 2 * tl;
    const int c2 = (tl >= 1) ? (2 * tl - 1) : 0;
    const int r1 = c1 % R, i1 = c1 / R;
    const int r2 = c2 % R, i2 = c2 / R;

    float x1 = la[0], x2 = la[0];
#pragma unroll
    for (int r = 1; r < R; ++r) {
        if (r == r1) x1 = la[r];
        if (r == r2) x2 = la[r];
    }
    x1 = __shfl_sync(FULL, x1, i1);
    x2 = __shfl_sync(FULL, x2, i2);

    if (lane == 0) {
        if (tl < 1) x2 = NEGF;
        const float m = fmaxf(x1, x2);
        float loss = -LN2 * (m + lg2f(ex2f(x1 - m) + ex2f(x2 - m)));
        if (!(loss < 5.0e29f)) loss = 0.0f;        // zero_infinity (inf/nan -> 0)
        g_loss[b] = loss;
    }
}

__global__ void ctc_reduce_kernel(float* __restrict__ out, int B)
{
    float s = 0.0f;
    for (int i = threadIdx.x; i < B; i += 32) s += g_loss[i];
#pragma unroll
    for (int o = 16; o; o >>= 1) s += __shfl_xor_sync(0xffffffffu, s, o);
    if (threadIdx.x == 0) out[0] = s;
}

extern "C" void kernel_launch(void* const* d_in, const int* in_sizes, int n_in,
                              void* d_out, int out_size)
{
    const float* logp        = (const float*)d_in[0];
    const int*   targets     = (const int*)  d_in[1];
    const int*   input_lens  = (const int*)  d_in[2];
    const int*   target_lens = (const int*)  d_in[3];

    const int B = in_sizes[2];
    const int S = in_sizes[1] / B;
    const int C = 1000;
    const int T = (int)((long long)in_sizes[0] / ((long long)B * (long long)C));

    const int L = 2 * S + 1;              // requires L <= 224 (S <= 111)

    ctc_emit_kernel<<<T * B, LPAD>>>(logp, targets, target_lens, B, C, S, L);
    ctc_alpha_kernel<<<B, 32>>>(targets, input_lens, target_lens, B, S);
    ctc_reduce_kernel<<<1, 32>>>((float*)d_out, B);
}

// round 8
// speedup vs baseline: 1.5356x; 1.5305x over previous
#include <cuda_runtime.h>

// ---------------------------------------------------------------------------
// CTC loss (forward, sum over batch, zero_infinity) on GB300 — two-phase,
// single-warp LOG2-domain scan (registers only, no barriers, no smem).
//
// Phase 1 (ctc_emit_kernel): em[t][b][l] = logp[t][b][ext_b[l]] * log2(e),
//   stored interleaved g_em[z*LPAD + r*32 + lane], column l = lane*R + r.
//
// Phase 2 (ctc_alpha_kernel): ONE WARP per batch element, lane i owns columns
//   [i*R, i*R+R). log2-alphas in registers; halo via 2 shfl_up; lse3 with
//   exact median-of-3 (ex2 args <= 0: overflow/NaN free, unbounded range).
//
//   KEY FIX this round: the prefetch-pipeline loop contains NO data-dependent
//   control flow (no break), so it fully unrolls and em[][] stays in
//   REGISTERS (a broken unroll demotes it to local memory -> ~1000 cyc/step).
//   Main loop processes full PF-chunks; a scalar tail loop handles the rest.
//   g_em is padded by PF timesteps so refill loads are unconditional.
// ---------------------------------------------------------------------------

#define NEGF (-1.0e30f)
#define LOG2E 1.4426950408889634f
#define LN2   0.6931471805599453f
#define R     7
#define LPAD  (32 * R)                  // 224 padded columns
#define PFD   8                         // prefetch pipeline depth
#define EM_CAP ((1000 + PFD) * 32 * LPAD)

__device__ __align__(128) float g_em[EM_CAP];
__device__ float g_loss[8192];

__device__ __forceinline__ float ex2f(float x) {
    float r; asm("ex2.approx.f32 %0, %1;" : "=f"(r) : "f"(x)); return r;
}
__device__ __forceinline__ float lg2f(float x) {
    float r; asm("lg2.approx.f32 %0, %1;" : "=f"(r) : "f"(x)); return r;
}

// lse3 in log2 domain; exact median-of-3 -> ex2 args provably <= 0.
__device__ __forceinline__ float lse3_2(float a0, float a1, float a2) {
    const float mx01 = fmaxf(a0, a1);
    const float mn01 = fminf(a0, a1);
    const float mx   = fmaxf(mx01, a2);
    const float md   = fmaxf(mn01, fminf(mx01, a2));
    const float mn   = fminf(mn01, a2);
    const float s    = 1.0f + ex2f(md - mx) + ex2f(mn - mx);
    return mx + lg2f(s);
}

// ---- Phase 1: emit gather (log2 units), one CTA per (t, b) pair ------------
__global__ void ctc_emit_kernel(const float* __restrict__ logp,
                                const int*   __restrict__ targets,
                                const int*   __restrict__ target_lens,
                                int B, int C, int S, int L)
{
    const int z = blockIdx.x;          // z = t*B + b
    const int b = z % B;
    const int l = threadIdx.x;         // 0 .. LPAD-1

    const int Lb = 2 * target_lens[b] + 1;

    float p = 0.0f;
    if (l < L && l < Lb) {
        int e = 0;
        if (l & 1) e = targets[b * S + (l >> 1)];
        p = logp[(size_t)z * C + e] * LOG2E;
    }
    g_em[((size_t)z * R + (l % R)) * 32 + (l / R)] = p;
}

// ---- Phase 2: single-warp log-domain alpha scan ------------------------------
__global__ void __launch_bounds__(32, 1)
ctc_alpha_kernel(const int* __restrict__ targets,
                 const int* __restrict__ input_lens,
                 const int* __restrict__ target_lens,
                 int B, int S)
{
    const int b    = blockIdx.x;
    const int lane = threadIdx.x;
    const unsigned FULL = 0xffffffffu;

    const int tl = target_lens[b];
    const int il = input_lens[b];
    const int Lb = 2 * tl + 1;

    // Skip-transition flags for this lane's columns.
    bool sk[R];
#pragma unroll
    for (int r = 0; r < R; ++r) {
        const int l = lane * R + r;
        bool s = false;
        if ((l & 1) && l >= 3 && l < Lb) {
            const int c  = targets[b * S + (l >> 1)];
            const int pc = targets[b * S + (l >> 1) - 1];
            s = (c != pc);
        }
        sk[r] = s;
    }

    const size_t strideT = (size_t)B * LPAD;
    const float* emp = g_em + (size_t)b * LPAD + lane;   // + r*32 + t*strideT

    // t = 0 init: log-alpha = em at columns 0,1 (lane 0), else -1e30.
    float la[R];
#pragma unroll
    for (int r = 0; r < R; ++r) la[r] = NEGF;
    {
        const float e00 = emp[0];       // coalesced; only lane 0's values used
        const float e01 = emp[32];
        if (lane == 0) { la[0] = e00; la[1] = e01; }
    }

    // Emit prefetch pipeline, depth PFD, strictly register-indexed.
    float em[PFD][R];
#pragma unroll
    for (int j = 0; j < PFD; ++j) {
#pragma unroll
        for (int r = 0; r < R; ++r)
            em[j][r] = emp[(size_t)(1 + j) * strideT + r * 32];  // padded: always in-bounds
    }

    // ---- Main loop: full PFD-chunks only; NO data-dependent control flow ----
    int tb = 1;
    for (; tb + PFD <= il; tb += PFD) {
#pragma unroll
        for (int j = 0; j < PFD; ++j) {
            const int t = tb + j;

            // Consume this step's emit row.
            const float e0 = em[j][0], e1 = em[j][1], e2c = em[j][2],
                        e3 = em[j][3], e4 = em[j][4], e5 = em[j][5],
                        e6 = em[j][6];

            // Refill the slot for t + PFD (padded array: unconditional).
            {
                const float* pf = emp + (size_t)(t + PFD) * strideT;
#pragma unroll
                for (int r = 0; r < R; ++r) em[j][r] = pf[r * 32];
            }

            // Halo: left lane's two rightmost OLD log-alphas.
            float L1 = __shfl_up_sync(FULL, la[R - 1], 1);
            float L2 = __shfl_up_sync(FULL, la[R - 2], 1);
            if (lane == 0) { L1 = NEGF; L2 = NEGF; }

            // In-place descending update: new la[r] uses only OLD la[<r].
            la[6] = lse3_2(la[6], la[5], sk[6] ? la[4] : NEGF) + e6;
            la[5] = lse3_2(la[5], la[4], sk[5] ? la[3] : NEGF) + e5;
            la[4] = lse3_2(la[4], la[3], sk[4] ? la[2] : NEGF) + e4;
            la[3] = lse3_2(la[3], la[2], sk[3] ? la[1] : NEGF) + e3;
            la[2] = lse3_2(la[2], la[1], sk[2] ? la[0] : NEGF) + e2c;
            la[1] = lse3_2(la[1], la[0], sk[1] ? L1    : NEGF) + e1;
            la[0] = lse3_2(la[0], L1,    sk[0] ? L2    : NEGF) + e0;
        }
    }

    // ---- Tail: remaining < PFD steps, direct loads (cost negligible) ----
    for (int t = tb; t < il; ++t) {
        const float* pf = emp + (size_t)t * strideT;
        float e[R];
#pragma unroll
        for (int r = 0; r < R; ++r) e[r] = pf[r * 32];

        float L1 = __shfl_up_sync(FULL, la[R - 1], 1);
        float L2 = __shfl_up_sync(FULL, la[R - 2], 1);
        if (lane == 0) { L1 = NEGF; L2 = NEGF; }

        la[6] = lse3_2(la[6], la[5], sk[6] ? la[4] : NEGF) + e[6];
        la[5] = lse3_2(la[5], la[4], sk[5] ? la[3] : NEGF) + e[5];
        la[4] = lse3_2(la[4], la[3], sk[4] ? la[2] : NEGF) + e[4];
        la[3] = lse3_2(la[3], la[2], sk[3] ? la[1] : NEGF) + e[3];
        la[2] = lse3_2(la[2], la[1], sk[2] ? la[0] : NEGF) + e[2];
        la[1] = lse3_2(la[1], la[0], sk[1] ? L1    : NEGF) + e[1];
        la[0] = lse3_2(la[0], L1,    sk[0] ? L2    : NEGF) + e[0];
    }

    // Final cells: columns 2*tl (blank) and 2*tl-1 (last label), log2 units.
    const int c1 = 2 * tl;
    const int c2 = (tl >= 1) ? (2 * tl - 1) : 0;
    const int r1 = c1 % R, i1 = c1 / R;
    const int r2 = c2 % R, i2 = c2 / R;

    float x1 = la[0], x2 = la[0];
#pragma unroll
    for (int r = 1; r < R; ++r) {
        if (r == r1) x1 = la[r];
        if (r == r2) x2 = la[r];
    }
    x1 = __shfl_sync(FULL, x1, i1);
    x2 = __shfl_sync(FULL, x2, i2);

    if (lane == 0) {
        if (tl < 1) x2 = NEGF;
        const float m = fmaxf(x1, x2);
        float loss = -LN2 * (m + lg2f(ex2f(x1 - m) + ex2f(x2 - m)));
        if (!(loss < 5.0e29f)) loss = 0.0f;        // zero_infinity (inf/nan -> 0)
        g_loss[b] = loss;
    }
}

__global__ void ctc_reduce_kernel(float* __restrict__ out, int B)
{
    float s = 0.0f;
    for (int i = threadIdx.x; i < B; i += 32) s += g_loss[i];
#pragma unroll
    for (int o = 16; o; o >>= 1) s += __shfl_xor_sync(0xffffffffu, s, o);
    if (threadIdx.x == 0) out[0] = s;
}

extern "C" void kernel_launch(void* const* d_in, const int* in_sizes, int n_in,
                              void* d_out, int out_size)
{
    const float* logp        = (const float*)d_in[0];
    const int*   targets     = (const int*)  d_in[1];
    const int*   input_lens  = (const int*)  d_in[2];
    const int*   target_lens = (const int*)  d_in[3];

    const int B = in_sizes[2];
    const int S = in_sizes[1] / B;
    const int C = 1000;
    const int T = (int)((long long)in_sizes[0] / ((long long)B * (long long)C));

    const int L = 2 * S + 1;              // requires L <= 224 (S <= 111)

    ctc_emit_kernel<<<T * B, LPAD>>>(logp, targets, target_lens, B, C, S, L);
    ctc_alpha_kernel<<<B, 32>>>(targets, input_lens, target_lens, B, S);
    ctc_reduce_kernel<<<1, 32>>>((float*)d_out, B);
}

// round 9
// speedup vs baseline: 1.6431x; 1.0700x over previous
#include <cuda_runtime.h>

// ---------------------------------------------------------------------------
// CTC loss (forward, sum over batch, zero_infinity) on GB300 — two-phase,
// single-warp LOG2-domain scan (registers only, no barriers, no smem).
//
// Phase 1 (ctc_emit_kernel): em[t][b][l] = logp[t][b][ext_b[l]] * log2(e),
//   packed 8 floats per (t,b,lane): g_em[((t*B+b)*32 + lane)*8 + r],
//   column l = lane*7 + r (r in 0..6; slot 7 is padding, never consumed).
//   logp is read with __ldcs (evict-first) so the 128MB logp stream does NOT
//   evict g_em (33MB) from L2 — alpha then hits L2 instead of DRAM.
//
// Phase 2 (ctc_alpha_kernel): ONE WARP per batch element, lane i owns columns
//   [i*7, i*7+7). log2-alphas in registers; halo via 2 shfl_up; lse3 with
//   exact median-of-3 (ex2 args <= 0: overflow/NaN free, unbounded range).
//   Emit rows loaded as 2x LDG.128 per step (few scoreboard slots), register
//   pipeline depth PFD=8, NO data-dependent control flow in the unrolled body
//   (keeps em[][] in registers). Final batch-sum reduction is fused in via a
//   threadfence + atomic counter (last block reduces g_loss -> out).
// ---------------------------------------------------------------------------

#define NEGF (-1.0e30f)
#define LOG2E 1.4426950408889634f
#define LN2   0.6931471805599453f
#define R     7
#define PFD   8                         // prefetch pipeline depth
#define EM_CAP ((1000 + PFD) * 32 * 32 * 8)   // (T+PFD) * B * 32 lanes * 8

__device__ __align__(128) float g_em[EM_CAP];
__device__ float g_loss[8192];
__device__ unsigned g_done;             // zero-initialized; reset after each pass

__device__ __forceinline__ float ex2f(float x) {
    float r; asm("ex2.approx.f32 %0, %1;" : "=f"(r) : "f"(x)); return r;
}
__device__ __forceinline__ float lg2f(float x) {
    float r; asm("lg2.approx.f32 %0, %1;" : "=f"(r) : "f"(x)); return r;
}

// lse3 in log2 domain; exact median-of-3 -> ex2 args provably <= 0.
__device__ __forceinline__ float lse3_2(float a0, float a1, float a2) {
    const float mx01 = fmaxf(a0, a1);
    const float mn01 = fminf(a0, a1);
    const float mx   = fmaxf(mx01, a2);
    const float md   = fmaxf(mn01, fminf(mx01, a2));
    const float mn   = fminf(mn01, a2);
    const float s    = 1.0f + ex2f(md - mx) + ex2f(mn - mx);
    return mx + lg2f(s);
}

// ---- Phase 1: emit gather (log2 units), one CTA per (t, b) pair ------------
__global__ void ctc_emit_kernel(const float* __restrict__ logp,
                                const int*   __restrict__ targets,
                                const int*   __restrict__ target_lens,
                                int B, int C, int S, int L)
{
    const int z = blockIdx.x;          // z = t*B + b
    const int b = z % B;
    const int l = threadIdx.x;         // 0 .. 223

    const int Lb = 2 * target_lens[b] + 1;

    float p = 0.0f;
    if (l < L && l < Lb) {
        int e = 0;
        if (l & 1) e = targets[b * S + (l >> 1)];
        p = __ldcs(&logp[(size_t)z * C + e]) * LOG2E;   // evict-first stream
    }
    const int lane = l / R;
    const int r    = l % R;
    g_em[(((size_t)z * 32) + lane) * 8 + r] = p;
}

// ---- Phase 2: single-warp log-domain alpha scan + fused reduction ----------
__global__ void __launch_bounds__(32, 1)
ctc_alpha_kernel(const int* __restrict__ targets,
                 const int* __restrict__ input_lens,
                 const int* __restrict__ target_lens,
                 float* __restrict__ out,
                 int B, int S)
{
    const int b    = blockIdx.x;
    const int lane = threadIdx.x;
    const unsigned FULL = 0xffffffffu;

    const int tl = target_lens[b];
    const int il = input_lens[b];
    const int Lb = 2 * tl + 1;

    // Skip-transition flags for this lane's columns.
    bool sk[R];
#pragma unroll
    for (int r = 0; r < R; ++r) {
        const int l = lane * R + r;
        bool s = false;
        if ((l & 1) && l >= 3 && l < Lb) {
            const int c  = targets[b * S + (l >> 1)];
            const int pc = targets[b * S + (l >> 1) - 1];
            s = (c != pc);
        }
        sk[r] = s;
    }

    const size_t strideT = (size_t)B * 256;                 // floats per timestep
    const float* base = g_em + ((size_t)b * 32 + lane) * 8; // + t*strideT

    // t = 0 init: log-alpha = em at columns 0,1 (lane 0), else -1e30.
    float la[R];
#pragma unroll
    for (int r = 0; r < R; ++r) la[r] = NEGF;
    if (lane == 0) { la[0] = base[0]; la[1] = base[1]; }

    // Emit prefetch pipeline: 2x float4 per step, register-indexed only.
    float4 em4[PFD][2];
#pragma unroll
    for (int j = 0; j < PFD; ++j) {
        const float4* p = (const float4*)(base + (size_t)(1 + j) * strideT);
        em4[j][0] = p[0];
        em4[j][1] = p[1];
    }

    // ---- Main loop: full PFD-chunks; NO data-dependent control flow --------
    int tb = 1;
    for (; tb + PFD <= il; tb += PFD) {
#pragma unroll
        for (int j = 0; j < PFD; ++j) {
            const int t = tb + j;

            // Consume this step's emit row.
            const float e0 = em4[j][0].x, e1 = em4[j][0].y,
                        e2 = em4[j][0].z, e3 = em4[j][0].w,
                        e4 = em4[j][1].x, e5 = em4[j][1].y,
                        e6 = em4[j][1].z;

            // Refill slot for t + PFD (padded array: unconditional).
            {
                const float4* p = (const float4*)(base + (size_t)(t + PFD) * strideT);
                em4[j][0] = p[0];
                em4[j][1] = p[1];
            }

            // Halo: left lane's two rightmost OLD log-alphas.
            float L1 = __shfl_up_sync(FULL, la[R - 1], 1);
            float L2 = __shfl_up_sync(FULL, la[R - 2], 1);
            if (lane == 0) { L1 = NEGF; L2 = NEGF; }

            // In-place descending update: new la[r] uses only OLD la[<r].
            la[6] = lse3_2(la[6], la[5], sk[6] ? la[4] : NEGF) + e6;
            la[5] = lse3_2(la[5], la[4], sk[5] ? la[3] : NEGF) + e5;
            la[4] = lse3_2(la[4], la[3], sk[4] ? la[2] : NEGF) + e4;
            la[3] = lse3_2(la[3], la[2], sk[3] ? la[1] : NEGF) + e3;
            la[2] = lse3_2(la[2], la[1], sk[2] ? la[0] : NEGF) + e2;
            la[1] = lse3_2(la[1], la[0], sk[1] ? L1    : NEGF) + e1;
            la[0] = lse3_2(la[0], L1,    sk[0] ? L2    : NEGF) + e0;
        }
    }

    // ---- Tail: remaining < PFD steps, direct loads --------------------------
    for (int t = tb; t < il; ++t) {
        const float4* p = (const float4*)(base + (size_t)t * strideT);
        const float4 q0 = p[0];
        const float4 q1 = p[1];

        float L1 = __shfl_up_sync(FULL, la[R - 1], 1);
        float L2 = __shfl_up_sync(FULL, la[R - 2], 1);
        if (lane == 0) { L1 = NEGF; L2 = NEGF; }

        la[6] = lse3_2(la[6], la[5], sk[6] ? la[4] : NEGF) + q1.z;
        la[5] = lse3_2(la[5], la[4], sk[5] ? la[3] : NEGF) + q1.y;
        la[4] = lse3_2(la[4], la[3], sk[4] ? la[2] : NEGF) + q1.x;
        la[3] = lse3_2(la[3], la[2], sk[3] ? la[1] : NEGF) + q0.w;
        la[2] = lse3_2(la[2], la[1], sk[2] ? la[0] : NEGF) + q0.z;
        la[1] = lse3_2(la[1], la[0], sk[1] ? L1    : NEGF) + q0.y;
        la[0] = lse3_2(la[0], L1,    sk[0] ? L2    : NEGF) + q0.x;
    }

    // Final cells: columns 2*tl (blank) and 2*tl-1 (last label), log2 units.
    const int c1 = 2 * tl;
    const int c2 = (tl >= 1) ? (2 * tl - 1) : 0;
    const int r1 = c1 % R, i1 = c1 / R;
    const int r2 = c2 % R, i2 = c2 / R;

    float x1 = la[0], x2 = la[0];
#pragma unroll
    for (int r = 1; r < R; ++r) {
        if (r == r1) x1 = la[r];
        if (r == r2) x2 = la[r];
    }
    x1 = __shfl_sync(FULL, x1, i1);
    x2 = __shfl_sync(FULL, x2, i2);

    int last = 0;
    if (lane == 0) {
        if (tl < 1) x2 = NEGF;
        const float m = fmaxf(x1, x2);
        float loss = -LN2 * (m + lg2f(ex2f(x1 - m) + ex2f(x2 - m)));
        if (!(loss < 5.0e29f)) loss = 0.0f;        // zero_infinity (inf/nan -> 0)
        g_loss[b] = loss;
        __threadfence();
        const unsigned n = atomicAdd(&g_done, 1u);
        last = (n == (unsigned)(gridDim.x - 1));
    }

    // Last-arriving block reduces g_loss -> out[0] and resets the counter.
    last = __shfl_sync(FULL, last, 0);
    if (last) {
        float s = 0.0f;
        for (int i = lane; i < B; i += 32) s += g_loss[i];
#pragma unroll
        for (int o = 16; o; o >>= 1) s += __shfl_xor_sync(FULL, s, o);
        if (lane == 0) {
            out[0] = s;
            g_done = 0u;                 // reset for the next (replayed) pass
        }
    }
}

extern "C" void kernel_launch(void* const* d_in, const int* in_sizes, int n_in,
                              void* d_out, int out_size)
{
    const float* logp        = (const float*)d_in[0];
    const int*   targets     = (const int*)  d_in[1];
    const int*   input_lens  = (const int*)  d_in[2];
    const int*   target_lens = (const int*)  d_in[3];

    const int B = in_sizes[2];
    const int S = in_sizes[1] / B;
    const int C = 1000;
    const int T = (int)((long long)in_sizes[0] / ((long long)B * (long long)C));

    const int L = 2 * S + 1;              // requires L <= 224 (S <= 111)

    ctc_emit_kernel<<<T * B, 224>>>(logp, targets, target_lens, B, C, S, L);
    ctc_alpha_kernel<<<B, 32>>>(targets, input_lens, target_lens,
                                (float*)d_out, B, S);
}

// round 10
// speedup vs baseline: 1.7605x; 1.0715x over previous
#include <cuda_runtime.h>
#include <cstdint>

// ---------------------------------------------------------------------------
// CTC loss (forward, sum over batch, zero_infinity) on GB300 — two-phase,
// single-warp LOG2-domain scan with a cp.async SMEM ring-buffer pipeline.
//
// Phase 1 (ctc_emit_kernel): em[t][b][l] = logp[t][b][ext_b[l]] * log2(e),
//   packed 8 floats per (t,b,lane): g_em[((t*B+b)*32 + lane)*8 + r],
//   column l = lane*7 + r (r in 0..6; slot 7 is padding).
//
// Phase 2 (ctc_alpha_kernel): ONE WARP per batch element, lane i owns columns
//   [i*7, i*7+7). log2-alphas in registers; halo via 2 shfl_up; lse3 with
//   exact median-of-3 (ex2 args <= 0: overflow/NaN free).
//
//   KEY FIX this round: emit prefetch uses cp.async into a 32-deep SMEM ring
//   with commit-group completion (wait_group<30>). Plain-LDG register
//   pipelines collapse onto ptxas's 6 scoreboard slots -> ~500cyc exposed
//   per step (measured 680 cyc/step); commit groups give true 32-step-deep
//   cover with no scoreboard pressure. 1-step register stage hides LDS.
// ---------------------------------------------------------------------------

#define NEGF (-1.0e30f)
#define LOG2E 1.4426950408889634f
#define LN2   0.6931471805599453f
#define R     7
#define DD    32                        // ring depth (power of two)
#define DMASK (DD - 1)
#define EM_CAP ((1000 + DD + 2) * 32 * 32 * 8)   // (T+DD+2) * B * 32 lanes * 8

__device__ __align__(128) float g_em[EM_CAP];
__device__ float g_loss[8192];
__device__ unsigned g_done;

__device__ __forceinline__ float ex2f(float x) {
    float r; asm("ex2.approx.f32 %0, %1;" : "=f"(r) : "f"(x)); return r;
}
__device__ __forceinline__ float lg2f(float x) {
    float r; asm("lg2.approx.f32 %0, %1;" : "=f"(r) : "f"(x)); return r;
}
__device__ __forceinline__ void cp16(uint32_t dst, const float* src) {
    asm volatile("cp.async.cg.shared.global [%0], [%1], 16;"
                 :: "r"(dst), "l"(src) : "memory");
}
__device__ __forceinline__ void cp_commit() {
    asm volatile("cp.async.commit_group;" ::: "memory");
}
template <int N>
__device__ __forceinline__ void cp_wait() {
    asm volatile("cp.async.wait_group %0;" :: "n"(N) : "memory");
}

// lse3 in log2 domain; exact median-of-3 -> ex2 args provably <= 0.
__device__ __forceinline__ float lse3_2(float a0, float a1, float a2) {
    const float mx01 = fmaxf(a0, a1);
    const float mn01 = fminf(a0, a1);
    const float mx   = fmaxf(mx01, a2);
    const float md   = fmaxf(mn01, fminf(mx01, a2));
    const float mn   = fminf(mn01, a2);
    const float s    = 1.0f + ex2f(md - mx) + ex2f(mn - mx);
    return mx + lg2f(s);
}

// ---- Phase 1: emit gather (log2 units), one CTA per (t, b) pair ------------
__global__ void ctc_emit_kernel(const float* __restrict__ logp,
                                const int*   __restrict__ targets,
                                const int*   __restrict__ target_lens,
                                int B, int C, int S, int L)
{
    const int z = blockIdx.x;          // z = t*B + b
    const int b = z % B;
    const int l = threadIdx.x;         // 0 .. 223

    const int Lb = 2 * target_lens[b] + 1;

    float p = 0.0f;
    if (l < L && l < Lb) {
        int e = 0;
        if (l & 1) e = targets[b * S + (l >> 1)];
        p = __ldcs(&logp[(size_t)z * C + e]) * LOG2E;
    }
    const int lane = l / R;
    const int r    = l % R;
    g_em[(((size_t)z * 32) + lane) * 8 + r] = p;
}

// ---- Phase 2: single-warp log-domain alpha scan + fused reduction ----------
__global__ void __launch_bounds__(32, 1)
ctc_alpha_kernel(const int* __restrict__ targets,
                 const int* __restrict__ input_lens,
                 const int* __restrict__ target_lens,
                 float* __restrict__ out,
                 int B, int S)
{
    __shared__ __align__(16) float ring[DD][32][8];   // 32 KB

    const int b    = blockIdx.x;
    const int lane = threadIdx.x;
    const unsigned FULL = 0xffffffffu;

    const int tl = target_lens[b];
    const int il = input_lens[b];
    const int Lb = 2 * tl + 1;

    // Skip-transition flags for this lane's columns.
    bool sk[R];
#pragma unroll
    for (int r = 0; r < R; ++r) {
        const int l = lane * R + r;
        bool s = false;
        if ((l & 1) && l >= 3 && l < Lb) {
            const int c  = targets[b * S + (l >> 1)];
            const int pc = targets[b * S + (l >> 1) - 1];
            s = (c != pc);
        }
        sk[r] = s;
    }

    const size_t strideT = (size_t)B * 256;                 // floats per timestep
    const float* base = g_em + ((size_t)b * 32 + lane) * 8; // + t*strideT

    const uint32_t ring_base =
        (uint32_t)__cvta_generic_to_shared(&ring[0][0][0]) + (uint32_t)lane * 32u;

    // t = 0 init: log-alpha = em at columns 0,1 (lane 0), else -1e30.
    float la[R];
#pragma unroll
    for (int r = 0; r < R; ++r) la[r] = NEGF;
    if (lane == 0) { la[0] = base[0]; la[1] = base[1]; }

    // ---- Prologue: fill the ring with rows 1..DD (group g_{r-1} = row r) ---
#pragma unroll
    for (int s = 0; s < DD; ++s) {
        const float* src = base + (size_t)(1 + s) * strideT;
        const uint32_t dst = ring_base + (uint32_t)s * (32u * 32u);
        cp16(dst, src);
        cp16(dst + 16u, src + 4);
        cp_commit();
    }
    cp_wait<DD - 1>();                    // row 1 complete
    float4 r0 = *(const float4*)&ring[0][lane][0];
    float4 r1 = *(const float4*)&ring[0][lane][4];

    // ---- Main loop: full 8-chunks; no data-dependent control flow ----------
    int tb = 1;
    for (; tb + 8 <= il; tb += 8) {
#pragma unroll
        for (int j = 0; j < 8; ++j) {
            const int t = tb + j;

            // Refill slot (t-1)&DMASK (its row t was consumed into registers
            // at step t-1) with row t+DD; commit keeps group order = row order.
            {
                const float* src = base + (size_t)(t + DD) * strideT;
                const uint32_t dst =
                    ring_base + (uint32_t)((t - 1) & DMASK) * (32u * 32u);
                cp16(dst, src);
                cp16(dst + 16u, src + 4);
                cp_commit();
            }
            // Committed rows: 1..t+DD; allow DD-2 outstanding -> rows <= t+2 done.
            cp_wait<DD - 2>();

            // Stage row t+1 into registers (hides LDS latency).
            const int slot = t & DMASK;
            const float4 n0 = *(const float4*)&ring[slot][lane][0];
            const float4 n1 = *(const float4*)&ring[slot][lane][4];

            // Halo: left lane's two rightmost OLD log-alphas.
            float L1 = __shfl_up_sync(FULL, la[R - 1], 1);
            float L2 = __shfl_up_sync(FULL, la[R - 2], 1);
            if (lane == 0) { L1 = NEGF; L2 = NEGF; }

            // In-place descending update with row t (r0, r1).
            la[6] = lse3_2(la[6], la[5], sk[6] ? la[4] : NEGF) + r1.z;
            la[5] = lse3_2(la[5], la[4], sk[5] ? la[3] : NEGF) + r1.y;
            la[4] = lse3_2(la[4], la[3], sk[4] ? la[2] : NEGF) + r1.x;
            la[3] = lse3_2(la[3], la[2], sk[3] ? la[1] : NEGF) + r0.w;
            la[2] = lse3_2(la[2], la[1], sk[2] ? la[0] : NEGF) + r0.z;
            la[1] = lse3_2(la[1], la[0], sk[1] ? L1    : NEGF) + r0.y;
            la[0] = lse3_2(la[0], L1,    sk[0] ? L2    : NEGF) + r0.x;

            r0 = n0; r1 = n1;
        }
    }

    // ---- Tail: remaining < 8 steps, direct global loads ---------------------
    for (int t = tb; t < il; ++t) {
        const float* p = base + (size_t)t * strideT;
        const float4 q0 = *(const float4*)(p);
        const float4 q1 = *(const float4*)(p + 4);

        float L1 = __shfl_up_sync(FULL, la[R - 1], 1);
        float L2 = __shfl_up_sync(FULL, la[R - 2], 1);
        if (lane == 0) { L1 = NEGF; L2 = NEGF; }

        la[6] = lse3_2(la[6], la[5], sk[6] ? la[4] : NEGF) + q1.z;
        la[5] = lse3_2(la[5], la[4], sk[5] ? la[3] : NEGF) + q1.y;
        la[4] = lse3_2(la[4], la[3], sk[4] ? la[2] : NEGF) + q1.x;
        la[3] = lse3_2(la[3], la[2], sk[3] ? la[1] : NEGF) + q0.w;
        la[2] = lse3_2(la[2], la[1], sk[2] ? la[0] : NEGF) + q0.z;
        la[1] = lse3_2(la[1], la[0], sk[1] ? L1    : NEGF) + q0.y;
        la[0] = lse3_2(la[0], L1,    sk[0] ? L2    : NEGF) + q0.x;
    }
    cp_wait<0>();   // drain ring (unused tail groups) before exit

    // Final cells: columns 2*tl (blank) and 2*tl-1 (last label), log2 units.
    const int c1 = 2 * tl;
    const int c2 = (tl >= 1) ? (2 * tl - 1) : 0;
    const int r1i = c1 % R, i1 = c1 / R;
    const int r2i = c2 % R, i2 = c2 / R;

    float x1 = la[0], x2 = la[0];
#pragma unroll
    for (int r = 1; r < R; ++r) {
        if (r == r1i) x1 = la[r];
        if (r == r2i) x2 = la[r];
    }
    x1 = __shfl_sync(FULL, x1, i1);
    x2 = __shfl_sync(FULL, x2, i2);

    int last = 0;
    if (lane == 0) {
        if (tl < 1) x2 = NEGF;
        const float m = fmaxf(x1, x2);
        float loss = -LN2 * (m + lg2f(ex2f(x1 - m) + ex2f(x2 - m)));
        if (!(loss < 5.0e29f)) loss = 0.0f;        // zero_infinity
        g_loss[b] = loss;
        __threadfence();
        const unsigned n = atomicAdd(&g_done, 1u);
        last = (n == (unsigned)(gridDim.x - 1));
    }

    last = __shfl_sync(FULL, last, 0);
    if (last) {
        float s = 0.0f;
        for (int i = lane; i < B; i += 32) s += g_loss[i];
#pragma unroll
        for (int o = 16; o; o >>= 1) s += __shfl_xor_sync(FULL, s, o);
        if (lane == 0) {
            out[0] = s;
            g_done = 0u;
        }
    }
}

extern "C" void kernel_launch(void* const* d_in, const int* in_sizes, int n_in,
                              void* d_out, int out_size)
{
    const float* logp        = (const float*)d_in[0];
    const int*   targets     = (const int*)  d_in[1];
    const int*   input_lens  = (const int*)  d_in[2];
    const int*   target_lens = (const int*)  d_in[3];

    const int B = in_sizes[2];
    const int S = in_sizes[1] / B;
    const int C = 1000;
    const int T = (int)((long long)in_sizes[0] / ((long long)B * (long long)C));

    const int L = 2 * S + 1;              // requires L <= 224 (S <= 111)

    ctc_emit_kernel<<<T * B, 224>>>(logp, targets, target_lens, B, C, S, L);
    ctc_alpha_kernel<<<B, 32>>>(targets, input_lens, target_lens,
                                (float*)d_out, B, S);
}